// round 10
// baseline (speedup 1.0000x reference)
#include <cuda_runtime.h>
#include <cuda_fp16.h>
#include <cstdint>

// PairwiseL1Loss: x,y [256][4096] fp32.
// out[i] = -(1/D^2) * sum_j (sum_k|x_i-x_j|) * (sum_k|y_i-y_j|)
// Identity (fp16-rounded values, S from same rounded values):
//   sum_k|x_i-x_j| = 2*sum_k max(x_ik,x_jk) - S_i - S_j.
//
// CONV: fp32 -> fp16 copies + row sums (512 blocks).
// PA  : 32x32 pair tiles, upper-tri (36), k-split x16 -> grid 576, occ 4.
//       cp.async double-buffered staging. Addressing trick: j-side iterated in
//       PHYSICAL quad order (immediates; swizzle cancels into the logical-k
//       map), i-side unswizzled (broadcast reads can't conflict) with 8
//       precomputed XOR offsets -> ~1 address op per kq iteration.
//       Fused two-level last-block epilogue. 2 launches.

#define BB 256
#define DD 4096
#define TILE 32
#define NT (BB / TILE)                 // 8
#define NPT 36
#define KSPLIT 16
#define KPER (DD / KSPLIT)             // 256 halfs
#define KC 64                          // halfs per stage (128B rows)
#define NSTAGE (KPER / KC)             // 4

#define IBUF_BYTES 8192                // 64 rows x 128B (x rows 0-31, y rows 32-63)
#define YOFF 4096

__device__ __half g_hx[BB * DD];
__device__ __half g_hy[BB * DD];
__device__ float4 g_part[NPT * KSPLIT * TILE * (TILE / 2)];
__device__ float  g_final[BB * NT];
__device__ float  g_colpart[NPT * TILE];
__device__ float  g_Sx[BB];
__device__ float  g_Sy[BB];
__device__ unsigned int g_tilecnt[NPT];
__device__ unsigned int g_cnt = 0;

__constant__ int c_bi[NPT] = {0,0,0,0,0,0,0,0, 1,1,1,1,1,1,1, 2,2,2,2,2,2,
                              3,3,3,3,3, 4,4,4,4, 5,5,5, 6,6, 7};
__constant__ int c_bj[NPT] = {0,1,2,3,4,5,6,7, 1,2,3,4,5,6,7, 2,3,4,5,6,7,
                              3,4,5,6,7, 4,5,6,7, 5,6,7, 6,7, 7};

__device__ __forceinline__ __half2 acc8(__half2 acc, const uint4 u, const uint4 v)
{
    const __half2* a = (const __half2*)&u;
    const __half2* b = (const __half2*)&v;
    const __half2 m0 = __hmax2(a[0], b[0]);
    const __half2 m1 = __hmax2(a[1], b[1]);
    const __half2 m2 = __hmax2(a[2], b[2]);
    const __half2 m3 = __hmax2(a[3], b[3]);
    return __hadd2(acc, __hadd2(__hadd2(m0, m1), __hadd2(m2, m3)));
}

__device__ __forceinline__ float drain(__half2 h)
{
    const float2 f = __half22float2(h);
    return f.x + f.y;
}

// ---------- CONV ----------
__global__ void conv_kernel(const float* __restrict__ x,
                            const float* __restrict__ y)
{
    const int bid = blockIdx.x;            // 0..511
    const int row = bid & (BB - 1);
    const bool isY = bid >= BB;
    const int tid = threadIdx.x;           // 256
    const float4* src = (const float4*)((isY ? y : x) + (size_t)row * DD);
    uint2* dst = (uint2*)((isY ? g_hy : g_hx) + (size_t)row * DD);

    float s = 0.f;
    #pragma unroll
    for (int it = 0; it < DD / 4 / 256; it++) {
        const int v = tid + 256 * it;
        const float4 a = src[v];
        const __half2 h0 = __floats2half2_rn(a.x, a.y);
        const __half2 h1 = __floats2half2_rn(a.z, a.w);
        uint2 u;
        u.x = *(const unsigned*)&h0;
        u.y = *(const unsigned*)&h1;
        dst[v] = u;
        s += drain(h0) + drain(h1);
    }
    #pragma unroll
    for (int off = 16; off > 0; off >>= 1)
        s += __shfl_xor_sync(0xffffffffu, s, off);
    __shared__ float ws[8];
    if ((tid & 31) == 0) ws[tid >> 5] = s;
    __syncthreads();
    if (tid == 0) {
        float t = 0.f;
        #pragma unroll
        for (int w = 0; w < 8; w++) t += ws[w];
        (isY ? g_Sy : g_Sx)[row] = t;
    }
}

// ---------- PA (+ fused epilogue) ----------
__global__ __launch_bounds__(256, 4)
void pa_kernel(float* __restrict__ out)
{
    // [buf][64 rows (x:0-31, y:32-63)][8 quads of 16B]
    __shared__ char sI[2][IBUF_BYTES];     // i-side, UNSWIZZLED
    __shared__ char sJ[2][IBUF_BYTES];     // j-side, quad swizzled by (r>>1)&7
    __shared__ float sp[TILE][TILE + 1];
    __shared__ unsigned int s_ticket;

    const int pt = blockIdx.x / KSPLIT;
    const int kc = blockIdx.x % KSPLIT;
    const int bi = c_bi[pt], bj = c_bj[pt];
    const int tid = threadIdx.x;
    const int ti = tid >> 4;
    const int tj = tid & 15;
    const int tjk = tj & 7;

    // staging: sr = row 0..31, sq = quad 0..7
    const int sr = tid >> 3;
    const int sq = tid & 7;
    const int iOff = sr * 128 + sq * 16;                        // unswizzled
    const int jOff = sr * 128 + (sq ^ ((sr >> 1) & 7)) * 16;    // swizzled

    const __half* srcXI = g_hx + (size_t)(bi * TILE + sr) * DD + kc * KPER + sq * 8;
    const __half* srcXJ = g_hx + (size_t)(bj * TILE + sr) * DD + kc * KPER + sq * 8;
    const __half* srcYI = g_hy + (size_t)(bi * TILE + sr) * DD + kc * KPER + sq * 8;
    const __half* srcYJ = g_hy + (size_t)(bj * TILE + sr) * DD + kc * KPER + sq * 8;

    // 8 precomputed i-side quad byte-offsets: logical k of physical j-quad m
    int qoff[8];
    #pragma unroll
    for (int m = 0; m < 8; m++)
        qoff[m] = ((m ^ tjk) << 4);

    const __half2 hz = __floats2half2_rn(0.f, 0.f);
    __half2 hx00 = hz, hx01 = hz, hx10 = hz, hx11 = hz;
    __half2 hy00 = hz, hy01 = hz, hy10 = hz, hy11 = hz;
    float fx00 = 0.f, fx01 = 0.f, fx10 = 0.f, fx11 = 0.f;
    float fy00 = 0.f, fy01 = 0.f, fy10 = 0.f, fy11 = 0.f;

    // prefetch stage 0
    {
        const uint32_t dI = (uint32_t)__cvta_generic_to_shared(&sI[0][iOff]);
        const uint32_t dJ = (uint32_t)__cvta_generic_to_shared(&sJ[0][jOff]);
        asm volatile("cp.async.cg.shared.global [%0], [%1], 16;" :: "r"(dI),        "l"(srcXI));
        asm volatile("cp.async.cg.shared.global [%0], [%1], 16;" :: "r"(dI + YOFF), "l"(srcYI));
        asm volatile("cp.async.cg.shared.global [%0], [%1], 16;" :: "r"(dJ),        "l"(srcXJ));
        asm volatile("cp.async.cg.shared.global [%0], [%1], 16;" :: "r"(dJ + YOFF), "l"(srcYJ));
        asm volatile("cp.async.commit_group;");
    }

    #pragma unroll
    for (int st = 0; st < NSTAGE; st++) {
        asm volatile("cp.async.wait_group 0;");
        __syncthreads();

        if (st + 1 < NSTAGE) {
            const int nb = (st + 1) & 1;
            const int koff = (st + 1) * KC;
            const uint32_t dI = (uint32_t)__cvta_generic_to_shared(&sI[nb][iOff]);
            const uint32_t dJ = (uint32_t)__cvta_generic_to_shared(&sJ[nb][jOff]);
            asm volatile("cp.async.cg.shared.global [%0], [%1], 16;" :: "r"(dI),        "l"(srcXI + koff));
            asm volatile("cp.async.cg.shared.global [%0], [%1], 16;" :: "r"(dI + YOFF), "l"(srcYI + koff));
            asm volatile("cp.async.cg.shared.global [%0], [%1], 16;" :: "r"(dJ),        "l"(srcXJ + koff));
            asm volatile("cp.async.cg.shared.global [%0], [%1], 16;" :: "r"(dJ + YOFF), "l"(srcYJ + koff));
            asm volatile("cp.async.commit_group;");
        }

        const char* iP = &sI[st & 1][(2 * ti) * 128];
        const char* jP = &sJ[st & 1][(2 * tj) * 128];

        #pragma unroll
        for (int m = 0; m < 8; m++) {
            const char* iq = iP + qoff[m];     // one IADD, 4 loads via imms
            const uint4 xu0 = *(const uint4*)(iq);
            const uint4 xu1 = *(const uint4*)(iq + 128);
            const uint4 yu0 = *(const uint4*)(iq + YOFF);
            const uint4 yu1 = *(const uint4*)(iq + YOFF + 128);
            const uint4 xv0 = *(const uint4*)(jP + m * 16);
            const uint4 xv1 = *(const uint4*)(jP + 128 + m * 16);
            const uint4 yv0 = *(const uint4*)(jP + YOFF + m * 16);
            const uint4 yv1 = *(const uint4*)(jP + YOFF + 128 + m * 16);

            hx00 = acc8(hx00, xu0, xv0);  hx01 = acc8(hx01, xu0, xv1);
            hx10 = acc8(hx10, xu1, xv0);  hx11 = acc8(hx11, xu1, xv1);
            hy00 = acc8(hy00, yu0, yv0);  hy01 = acc8(hy01, yu0, yv1);
            hy10 = acc8(hy10, yu1, yv0);  hy11 = acc8(hy11, yu1, yv1);
        }

        fx00 += drain(hx00); hx00 = hz;   fx01 += drain(hx01); hx01 = hz;
        fx10 += drain(hx10); hx10 = hz;   fx11 += drain(hx11); hx11 = hz;
        fy00 += drain(hy00); hy00 = hz;   fy01 += drain(hy01); hy01 = hz;
        fy10 += drain(hy10); hy10 = hz;   fy11 += drain(hy11); hy11 = hz;
    }

    float4* gp = g_part + ((size_t)pt * KSPLIT + kc) * (TILE * (TILE / 2));
    gp[(2 * ti    ) * 16 + tj] = make_float4(fx00, fy00, fx01, fy01);
    gp[(2 * ti + 1) * 16 + tj] = make_float4(fx10, fy10, fx11, fy11);

    // ---- per-tile last-block election ----
    __threadfence();
    __syncthreads();
    if (tid == 0) s_ticket = atomicAdd(&g_tilecnt[pt], 1u);
    __syncthreads();
    if (s_ticket != KSPLIT - 1) return;
    if (tid == 0) g_tilecnt[pt] = 0;

    // ---- tile epilogue ----
    const float4* gpt = (const float4*)(g_part + (size_t)pt * KSPLIT * (TILE * (TILE / 2)));
    #pragma unroll
    for (int half = 0; half < 2; half++) {
        const int item = tid + 256 * half;
        const int r  = item >> 4;
        const int cp = item & 15;
        const int ig = bi * TILE + r;
        const int j0 = bj * TILE + 2 * cp;

        const float4* gpr = gpt + r * 16 + cp;
        float4 m = make_float4(0.f, 0.f, 0.f, 0.f);
        #pragma unroll
        for (int kcc = 0; kcc < KSPLIT; kcc++) {
            const float4 v = __ldcg(gpr + (size_t)kcc * (TILE * (TILE / 2)));
            m.x += v.x; m.y += v.y; m.z += v.z; m.w += v.w;
        }
        const float Sxi = g_Sx[ig], Syi = g_Sy[ig];
        const float sx0 = 2.0f * m.x - Sxi - g_Sx[j0];
        const float sy0 = 2.0f * m.y - Syi - g_Sy[j0];
        const float sx1 = 2.0f * m.z - Sxi - g_Sx[j0 + 1];
        const float sy1 = 2.0f * m.w - Syi - g_Sy[j0 + 1];
        const float p0 = sx0 * sy0;
        const float p1 = sx1 * sy1;

        sp[r][2 * cp]     = p0;
        sp[r][2 * cp + 1] = p1;

        float rs = p0 + p1;
        #pragma unroll
        for (int off = 8; off > 0; off >>= 1)
            rs += __shfl_xor_sync(0xffffffffu, rs, off);
        if (cp == 0)
            g_final[ig * NT + bj] = rs;
    }
    __syncthreads();

    if (tid < TILE) {
        float cs = 0.f;
        #pragma unroll
        for (int rr = 0; rr < TILE; rr++) cs += sp[rr][tid];
        g_colpart[pt * TILE + tid] = cs;
    }

    // ---- global last-tile election ----
    __threadfence();
    __syncthreads();
    if (tid == 0) s_ticket = atomicAdd(&g_cnt, 1u);
    __syncthreads();
    if (s_ticket != NPT - 1) return;

    {
        const int i  = tid;
        const int tb = i >> 5;
        const int c  = i & 31;
        float s = 0.f;
        #pragma unroll
        for (int t2 = 0; t2 < NT; t2++)
            if (t2 >= tb) s += __ldcg(&g_final[i * NT + t2]);
        for (int a = 0; a < tb; a++) {
            const int ptc = a * NT - (a * (a - 1)) / 2 + (tb - a);
            s += __ldcg(&g_colpart[ptc * TILE + c]);
        }
        out[i] = -s * (1.0f / ((float)DD * (float)DD));
    }
    __syncthreads();
    if (tid == 0) g_cnt = 0;
}

extern "C" void kernel_launch(void* const* d_in, const int* in_sizes, int n_in,
                              void* d_out, int out_size)
{
    const float* x = (const float*)d_in[0];
    const float* y = (const float*)d_in[1];
    float* out = (float*)d_out;

    conv_kernel<<<2 * BB, 256>>>(x, y);
    pa_kernel<<<NPT * KSPLIT, 256>>>(out);
}

// round 11
// speedup vs baseline: 2.9636x; 2.9636x over previous
#include <cuda_runtime.h>
#include <cuda_fp16.h>
#include <cstdint>

// PairwiseL1Loss: x,y [256][4096] fp32.
// out[i] = -(1/D^2) * sum_j (sum_k|x_i-x_j|) * (sum_k|y_i-y_j|)
// Identity (fp16-rounded values, S from same rounded values):
//   sum_k|x_i-x_j| = 2*sum_k max(x_ik,x_jk) - S_i - S_j.
//
// CONV: fp32 -> fp16 copies + row sums (512 blocks).
// PA  : 32x32 pair tiles, upper-tri (36), k-split x16 -> grid 576, occ 4.
//       R9 access scheme (logical-order kq + XOR swizzle; R10's physical-order
//       walk caused 8-way bank conflicts and regressed 3x). NEW: warp lane
//       geometry ti4 x tj8 halves j-side smem traffic (768B/warp-kq vs 1152)
//       and makes all LDS single-phase. Fused two-level last-block epilogue.

#define BB 256
#define DD 4096
#define TILE 32
#define NT (BB / TILE)                 // 8
#define NPT 36
#define KSPLIT 16
#define KPER (DD / KSPLIT)             // 256 halfs
#define KC 64                          // halfs per stage (128B rows)
#define NSTAGE (KPER / KC)             // 4

__device__ __half g_hx[BB * DD];
__device__ __half g_hy[BB * DD];
__device__ float4 g_part[NPT * KSPLIT * TILE * (TILE / 2)];
__device__ float  g_final[BB * NT];
__device__ float  g_colpart[NPT * TILE];
__device__ float  g_Sx[BB];
__device__ float  g_Sy[BB];
__device__ unsigned int g_tilecnt[NPT];
__device__ unsigned int g_cnt = 0;

__constant__ int c_bi[NPT] = {0,0,0,0,0,0,0,0, 1,1,1,1,1,1,1, 2,2,2,2,2,2,
                              3,3,3,3,3, 4,4,4,4, 5,5,5, 6,6, 7};
__constant__ int c_bj[NPT] = {0,1,2,3,4,5,6,7, 1,2,3,4,5,6,7, 2,3,4,5,6,7,
                              3,4,5,6,7, 4,5,6,7, 5,6,7, 6,7, 7};

__device__ __forceinline__ __half2 acc8(__half2 acc, const uint4 u, const uint4 v)
{
    const __half2* a = (const __half2*)&u;
    const __half2* b = (const __half2*)&v;
    const __half2 m0 = __hmax2(a[0], b[0]);
    const __half2 m1 = __hmax2(a[1], b[1]);
    const __half2 m2 = __hmax2(a[2], b[2]);
    const __half2 m3 = __hmax2(a[3], b[3]);
    return __hadd2(acc, __hadd2(__hadd2(m0, m1), __hadd2(m2, m3)));
}

__device__ __forceinline__ float drain(__half2 h)
{
    const float2 f = __half22float2(h);
    return f.x + f.y;
}

// ---------- CONV ----------
__global__ void conv_kernel(const float* __restrict__ x,
                            const float* __restrict__ y)
{
    const int bid = blockIdx.x;            // 0..511
    const int row = bid & (BB - 1);
    const bool isY = bid >= BB;
    const int tid = threadIdx.x;           // 256
    const float4* src = (const float4*)((isY ? y : x) + (size_t)row * DD);
    uint2* dst = (uint2*)((isY ? g_hy : g_hx) + (size_t)row * DD);

    float s = 0.f;
    #pragma unroll
    for (int it = 0; it < DD / 4 / 256; it++) {
        const int v = tid + 256 * it;
        const float4 a = src[v];
        const __half2 h0 = __floats2half2_rn(a.x, a.y);
        const __half2 h1 = __floats2half2_rn(a.z, a.w);
        uint2 u;
        u.x = *(const unsigned*)&h0;
        u.y = *(const unsigned*)&h1;
        dst[v] = u;
        s += drain(h0) + drain(h1);
    }
    #pragma unroll
    for (int off = 16; off > 0; off >>= 1)
        s += __shfl_xor_sync(0xffffffffu, s, off);
    __shared__ float ws[8];
    if ((tid & 31) == 0) ws[tid >> 5] = s;
    __syncthreads();
    if (tid == 0) {
        float t = 0.f;
        #pragma unroll
        for (int w = 0; w < 8; w++) t += ws[w];
        (isY ? g_Sy : g_Sx)[row] = t;
    }
}

// ---------- PA (+ fused epilogue) ----------
__global__ __launch_bounds__(256, 4)
void pa_kernel(float* __restrict__ out)
{
    __shared__ uint4 sbuf[2][4][TILE * 8];     // 32KB, quads swizzled q^((r>>1)&7)
    __shared__ float sp[TILE][TILE + 1];
    __shared__ unsigned int s_ticket;

    const int pt = blockIdx.x / KSPLIT;
    const int kc = blockIdx.x % KSPLIT;
    const int bi = c_bi[pt], bj = c_bj[pt];
    const int tid = threadIdx.x;

    // Warp lane geometry: ti4 x tj8 per warp (j-smem traffic halved,
    // all LDS single-phase). Bijective over 256 threads.
    const int lane = tid & 31;
    const int w = tid >> 5;
    const int ti = (w >> 1) * 4 + (lane >> 3);    // 0..15
    const int tj = (w & 1) * 8 + (lane & 7);      // 0..15
    const int tik = ti & 7;
    const int tjk = tj & 7;

    const int sr = tid >> 3;
    const int sq = tid & 7;
    const int ssw = sr * 8 + (sq ^ ((sr >> 1) & 7));

    const __half* srcXI = g_hx + (size_t)(bi * TILE + sr) * DD + kc * KPER + sq * 8;
    const __half* srcXJ = g_hx + (size_t)(bj * TILE + sr) * DD + kc * KPER + sq * 8;
    const __half* srcYI = g_hy + (size_t)(bi * TILE + sr) * DD + kc * KPER + sq * 8;
    const __half* srcYJ = g_hy + (size_t)(bj * TILE + sr) * DD + kc * KPER + sq * 8;

    const __half2 hz = __floats2half2_rn(0.f, 0.f);
    __half2 hx00 = hz, hx01 = hz, hx10 = hz, hx11 = hz;
    __half2 hy00 = hz, hy01 = hz, hy10 = hz, hy11 = hz;
    float fx00 = 0.f, fx01 = 0.f, fx10 = 0.f, fx11 = 0.f;
    float fy00 = 0.f, fy01 = 0.f, fy10 = 0.f, fy11 = 0.f;

    {
        const uint32_t d0 = (uint32_t)__cvta_generic_to_shared(&sbuf[0][0][ssw]);
        const uint32_t d1 = (uint32_t)__cvta_generic_to_shared(&sbuf[0][1][ssw]);
        const uint32_t d2 = (uint32_t)__cvta_generic_to_shared(&sbuf[0][2][ssw]);
        const uint32_t d3 = (uint32_t)__cvta_generic_to_shared(&sbuf[0][3][ssw]);
        asm volatile("cp.async.cg.shared.global [%0], [%1], 16;" :: "r"(d0), "l"(srcXI));
        asm volatile("cp.async.cg.shared.global [%0], [%1], 16;" :: "r"(d1), "l"(srcXJ));
        asm volatile("cp.async.cg.shared.global [%0], [%1], 16;" :: "r"(d2), "l"(srcYI));
        asm volatile("cp.async.cg.shared.global [%0], [%1], 16;" :: "r"(d3), "l"(srcYJ));
        asm volatile("cp.async.commit_group;");
    }

    #pragma unroll
    for (int st = 0; st < NSTAGE; st++) {
        asm volatile("cp.async.wait_group 0;");
        __syncthreads();

        if (st + 1 < NSTAGE) {
            const int nb = (st + 1) & 1;
            const int koff = (st + 1) * KC;
            const uint32_t d0 = (uint32_t)__cvta_generic_to_shared(&sbuf[nb][0][ssw]);
            const uint32_t d1 = (uint32_t)__cvta_generic_to_shared(&sbuf[nb][1][ssw]);
            const uint32_t d2 = (uint32_t)__cvta_generic_to_shared(&sbuf[nb][2][ssw]);
            const uint32_t d3 = (uint32_t)__cvta_generic_to_shared(&sbuf[nb][3][ssw]);
            asm volatile("cp.async.cg.shared.global [%0], [%1], 16;" :: "r"(d0), "l"(srcXI + koff));
            asm volatile("cp.async.cg.shared.global [%0], [%1], 16;" :: "r"(d1), "l"(srcXJ + koff));
            asm volatile("cp.async.cg.shared.global [%0], [%1], 16;" :: "r"(d2), "l"(srcYI + koff));
            asm volatile("cp.async.cg.shared.global [%0], [%1], 16;" :: "r"(d3), "l"(srcYJ + koff));
            asm volatile("cp.async.commit_group;");
        }

        const uint4* bxi = sbuf[st & 1][0];
        const uint4* bxj = sbuf[st & 1][1];
        const uint4* byi = sbuf[st & 1][2];
        const uint4* byj = sbuf[st & 1][3];

        #pragma unroll
        for (int kq = 0; kq < 8; kq++) {
            const int qi = kq ^ tik;
            const int qj = kq ^ tjk;
            {
                const uint4 u0 = bxi[(2 * ti    ) * 8 + qi];
                const uint4 u1 = bxi[(2 * ti + 1) * 8 + qi];
                const uint4 v0 = bxj[(2 * tj    ) * 8 + qj];
                const uint4 v1 = bxj[(2 * tj + 1) * 8 + qj];
                hx00 = acc8(hx00, u0, v0);  hx01 = acc8(hx01, u0, v1);
                hx10 = acc8(hx10, u1, v0);  hx11 = acc8(hx11, u1, v1);
            }
            {
                const uint4 u0 = byi[(2 * ti    ) * 8 + qi];
                const uint4 u1 = byi[(2 * ti + 1) * 8 + qi];
                const uint4 v0 = byj[(2 * tj    ) * 8 + qj];
                const uint4 v1 = byj[(2 * tj + 1) * 8 + qj];
                hy00 = acc8(hy00, u0, v0);  hy01 = acc8(hy01, u0, v1);
                hy10 = acc8(hy10, u1, v0);  hy11 = acc8(hy11, u1, v1);
            }
        }

        fx00 += drain(hx00); hx00 = hz;   fx01 += drain(hx01); hx01 = hz;
        fx10 += drain(hx10); hx10 = hz;   fx11 += drain(hx11); hx11 = hz;
        fy00 += drain(hy00); hy00 = hz;   fy01 += drain(hy01); hy01 = hz;
        fy10 += drain(hy10); hy10 = hz;   fy11 += drain(hy11); hy11 = hz;
    }

    float4* gp = g_part + ((size_t)pt * KSPLIT + kc) * (TILE * (TILE / 2));
    gp[(2 * ti    ) * 16 + tj] = make_float4(fx00, fy00, fx01, fy01);
    gp[(2 * ti + 1) * 16 + tj] = make_float4(fx10, fy10, fx11, fy11);

    // ---- per-tile last-block election ----
    __threadfence();
    __syncthreads();
    if (tid == 0) s_ticket = atomicAdd(&g_tilecnt[pt], 1u);
    __syncthreads();
    if (s_ticket != KSPLIT - 1) return;
    if (tid == 0) g_tilecnt[pt] = 0;

    // ---- tile epilogue ----
    const float4* gpt = (const float4*)(g_part + (size_t)pt * KSPLIT * (TILE * (TILE / 2)));
    #pragma unroll
    for (int half = 0; half < 2; half++) {
        const int item = tid + 256 * half;
        const int r  = item >> 4;
        const int cp = item & 15;
        const int ig = bi * TILE + r;
        const int j0 = bj * TILE + 2 * cp;

        const float4* gpr = gpt + r * 16 + cp;
        float4 m = make_float4(0.f, 0.f, 0.f, 0.f);
        #pragma unroll
        for (int kcc = 0; kcc < KSPLIT; kcc++) {
            const float4 v = __ldcg(gpr + (size_t)kcc * (TILE * (TILE / 2)));
            m.x += v.x; m.y += v.y; m.z += v.z; m.w += v.w;
        }
        const float Sxi = g_Sx[ig], Syi = g_Sy[ig];
        const float sx0 = 2.0f * m.x - Sxi - g_Sx[j0];
        const float sy0 = 2.0f * m.y - Syi - g_Sy[j0];
        const float sx1 = 2.0f * m.z - Sxi - g_Sx[j0 + 1];
        const float sy1 = 2.0f * m.w - Syi - g_Sy[j0 + 1];
        const float p0 = sx0 * sy0;
        const float p1 = sx1 * sy1;

        sp[r][2 * cp]     = p0;
        sp[r][2 * cp + 1] = p1;

        float rs = p0 + p1;
        #pragma unroll
        for (int off = 8; off > 0; off >>= 1)
            rs += __shfl_xor_sync(0xffffffffu, rs, off);
        if (cp == 0)
            g_final[ig * NT + bj] = rs;
    }
    __syncthreads();

    if (tid < TILE) {
        float cs = 0.f;
        #pragma unroll
        for (int rr = 0; rr < TILE; rr++) cs += sp[rr][tid];
        g_colpart[pt * TILE + tid] = cs;
    }

    // ---- global last-tile election ----
    __threadfence();
    __syncthreads();
    if (tid == 0) s_ticket = atomicAdd(&g_cnt, 1u);
    __syncthreads();
    if (s_ticket != NPT - 1) return;

    {
        const int i  = tid;
        const int tb = i >> 5;
        const int c  = i & 31;
        float s = 0.f;
        #pragma unroll
        for (int t2 = 0; t2 < NT; t2++)
            if (t2 >= tb) s += __ldcg(&g_final[i * NT + t2]);
        for (int a = 0; a < tb; a++) {
            const int ptc = a * NT - (a * (a - 1)) / 2 + (tb - a);
            s += __ldcg(&g_colpart[ptc * TILE + c]);
        }
        out[i] = -s * (1.0f / ((float)DD * (float)DD));
    }
    __syncthreads();
    if (tid == 0) g_cnt = 0;
}

extern "C" void kernel_launch(void* const* d_in, const int* in_sizes, int n_in,
                              void* d_out, int out_size)
{
    const float* x = (const float*)d_in[0];
    const float* y = (const float*)d_in[1];
    float* out = (float*)d_out;

    conv_kernel<<<2 * BB, 256>>>(x, y);
    pa_kernel<<<NPT * KSPLIT, 256>>>(out);
}

// round 12
// speedup vs baseline: 3.3545x; 1.1319x over previous
#include <cuda_runtime.h>
#include <cuda_fp16.h>
#include <cstdint>

// PairwiseL1Loss: x,y [256][4096] fp32.
// out[i] = -(1/D^2) * sum_j (sum_k|x_i-x_j|) * (sum_k|y_i-y_j|)
// Identity (fp16-rounded values, S from same rounded values):
//   sum_k|x_i-x_j| = 2*sum_k max(x_ik,x_jk) - S_i - S_j.
//
// CONV: fp32 -> fp16 copies + row sums (512 blocks).
// PA  : 32x32 pair tiles, upper-tri (36), k-split x8 -> grid 288, occ 2 ->
//       single wave WITH 128 regs/thread (R11 ran occ4/64regs and stalled at
//       IPC 0.4 from load serialization; pipes only 33%). cp.async double
//       buffering, XOR-swizzled smem, logical-order kq walk.
//       Fused two-level last-block epilogue. 2 launches.

#define BB 256
#define DD 4096
#define TILE 32
#define NT (BB / TILE)                 // 8
#define NPT 36
#define KSPLIT 8
#define KPER (DD / KSPLIT)             // 512 halfs
#define KC 64                          // halfs per stage (128B rows)
#define NSTAGE (KPER / KC)             // 8

__device__ __half g_hx[BB * DD];
__device__ __half g_hy[BB * DD];
__device__ float4 g_part[NPT * KSPLIT * TILE * (TILE / 2)];
__device__ float  g_final[BB * NT];
__device__ float  g_colpart[NPT * TILE];
__device__ float  g_Sx[BB];
__device__ float  g_Sy[BB];
__device__ unsigned int g_tilecnt[NPT];
__device__ unsigned int g_cnt = 0;

__constant__ int c_bi[NPT] = {0,0,0,0,0,0,0,0, 1,1,1,1,1,1,1, 2,2,2,2,2,2,
                              3,3,3,3,3, 4,4,4,4, 5,5,5, 6,6, 7};
__constant__ int c_bj[NPT] = {0,1,2,3,4,5,6,7, 1,2,3,4,5,6,7, 2,3,4,5,6,7,
                              3,4,5,6,7, 4,5,6,7, 5,6,7, 6,7, 7};

__device__ __forceinline__ __half2 acc8(__half2 acc, const uint4 u, const uint4 v)
{
    const __half2* a = (const __half2*)&u;
    const __half2* b = (const __half2*)&v;
    const __half2 m0 = __hmax2(a[0], b[0]);
    const __half2 m1 = __hmax2(a[1], b[1]);
    const __half2 m2 = __hmax2(a[2], b[2]);
    const __half2 m3 = __hmax2(a[3], b[3]);
    return __hadd2(acc, __hadd2(__hadd2(m0, m1), __hadd2(m2, m3)));
}

__device__ __forceinline__ float drain(__half2 h)
{
    const float2 f = __half22float2(h);
    return f.x + f.y;
}

// ---------- CONV ----------
__global__ void conv_kernel(const float* __restrict__ x,
                            const float* __restrict__ y)
{
    const int bid = blockIdx.x;            // 0..511
    const int row = bid & (BB - 1);
    const bool isY = bid >= BB;
    const int tid = threadIdx.x;           // 256
    const float4* src = (const float4*)((isY ? y : x) + (size_t)row * DD);
    uint2* dst = (uint2*)((isY ? g_hy : g_hx) + (size_t)row * DD);

    float s = 0.f;
    #pragma unroll
    for (int it = 0; it < DD / 4 / 256; it++) {
        const int v = tid + 256 * it;
        const float4 a = src[v];
        const __half2 h0 = __floats2half2_rn(a.x, a.y);
        const __half2 h1 = __floats2half2_rn(a.z, a.w);
        uint2 u;
        u.x = *(const unsigned*)&h0;
        u.y = *(const unsigned*)&h1;
        dst[v] = u;
        s += drain(h0) + drain(h1);
    }
    #pragma unroll
    for (int off = 16; off > 0; off >>= 1)
        s += __shfl_xor_sync(0xffffffffu, s, off);
    __shared__ float ws[8];
    if ((tid & 31) == 0) ws[tid >> 5] = s;
    __syncthreads();
    if (tid == 0) {
        float t = 0.f;
        #pragma unroll
        for (int w = 0; w < 8; w++) t += ws[w];
        (isY ? g_Sy : g_Sx)[row] = t;
    }
}

// ---------- PA (+ fused epilogue) ----------
__global__ __launch_bounds__(256, 2)
void pa_kernel(float* __restrict__ out)
{
    __shared__ uint4 sbuf[2][4][TILE * 8];     // 32KB, quads swizzled q^((r>>1)&7)
    __shared__ float sp[TILE][TILE + 1];
    __shared__ unsigned int s_ticket;

    const int pt = blockIdx.x / KSPLIT;
    const int kc = blockIdx.x % KSPLIT;
    const int bi = c_bi[pt], bj = c_bj[pt];
    const int tid = threadIdx.x;

    const int lane = tid & 31;
    const int w = tid >> 5;
    const int ti = (w >> 1) * 4 + (lane >> 3);    // 0..15
    const int tj = (w & 1) * 8 + (lane & 7);      // 0..15
    const int tik = ti & 7;
    const int tjk = tj & 7;

    const int sr = tid >> 3;
    const int sq = tid & 7;
    const int ssw = sr * 8 + (sq ^ ((sr >> 1) & 7));

    const __half* srcXI = g_hx + (size_t)(bi * TILE + sr) * DD + kc * KPER + sq * 8;
    const __half* srcXJ = g_hx + (size_t)(bj * TILE + sr) * DD + kc * KPER + sq * 8;
    const __half* srcYI = g_hy + (size_t)(bi * TILE + sr) * DD + kc * KPER + sq * 8;
    const __half* srcYJ = g_hy + (size_t)(bj * TILE + sr) * DD + kc * KPER + sq * 8;

    const __half2 hz = __floats2half2_rn(0.f, 0.f);
    __half2 hx00 = hz, hx01 = hz, hx10 = hz, hx11 = hz;
    __half2 hy00 = hz, hy01 = hz, hy10 = hz, hy11 = hz;
    float fx00 = 0.f, fx01 = 0.f, fx10 = 0.f, fx11 = 0.f;
    float fy00 = 0.f, fy01 = 0.f, fy10 = 0.f, fy11 = 0.f;

    {
        const uint32_t d0 = (uint32_t)__cvta_generic_to_shared(&sbuf[0][0][ssw]);
        const uint32_t d1 = (uint32_t)__cvta_generic_to_shared(&sbuf[0][1][ssw]);
        const uint32_t d2 = (uint32_t)__cvta_generic_to_shared(&sbuf[0][2][ssw]);
        const uint32_t d3 = (uint32_t)__cvta_generic_to_shared(&sbuf[0][3][ssw]);
        asm volatile("cp.async.cg.shared.global [%0], [%1], 16;" :: "r"(d0), "l"(srcXI));
        asm volatile("cp.async.cg.shared.global [%0], [%1], 16;" :: "r"(d1), "l"(srcXJ));
        asm volatile("cp.async.cg.shared.global [%0], [%1], 16;" :: "r"(d2), "l"(srcYI));
        asm volatile("cp.async.cg.shared.global [%0], [%1], 16;" :: "r"(d3), "l"(srcYJ));
        asm volatile("cp.async.commit_group;");
    }

    #pragma unroll
    for (int st = 0; st < NSTAGE; st++) {
        asm volatile("cp.async.wait_group 0;");
        __syncthreads();

        if (st + 1 < NSTAGE) {
            const int nb = (st + 1) & 1;
            const int koff = (st + 1) * KC;
            const uint32_t d0 = (uint32_t)__cvta_generic_to_shared(&sbuf[nb][0][ssw]);
            const uint32_t d1 = (uint32_t)__cvta_generic_to_shared(&sbuf[nb][1][ssw]);
            const uint32_t d2 = (uint32_t)__cvta_generic_to_shared(&sbuf[nb][2][ssw]);
            const uint32_t d3 = (uint32_t)__cvta_generic_to_shared(&sbuf[nb][3][ssw]);
            asm volatile("cp.async.cg.shared.global [%0], [%1], 16;" :: "r"(d0), "l"(srcXI + koff));
            asm volatile("cp.async.cg.shared.global [%0], [%1], 16;" :: "r"(d1), "l"(srcXJ + koff));
            asm volatile("cp.async.cg.shared.global [%0], [%1], 16;" :: "r"(d2), "l"(srcYI + koff));
            asm volatile("cp.async.cg.shared.global [%0], [%1], 16;" :: "r"(d3), "l"(srcYJ + koff));
            asm volatile("cp.async.commit_group;");
        }

        const uint4* bxi = sbuf[st & 1][0];
        const uint4* bxj = sbuf[st & 1][1];
        const uint4* byi = sbuf[st & 1][2];
        const uint4* byj = sbuf[st & 1][3];

        #pragma unroll
        for (int kq = 0; kq < 8; kq++) {
            const int qi = kq ^ tik;
            const int qj = kq ^ tjk;
            {
                const uint4 u0 = bxi[(2 * ti    ) * 8 + qi];
                const uint4 u1 = bxi[(2 * ti + 1) * 8 + qi];
                const uint4 v0 = bxj[(2 * tj    ) * 8 + qj];
                const uint4 v1 = bxj[(2 * tj + 1) * 8 + qj];
                hx00 = acc8(hx00, u0, v0);  hx01 = acc8(hx01, u0, v1);
                hx10 = acc8(hx10, u1, v0);  hx11 = acc8(hx11, u1, v1);
            }
            {
                const uint4 u0 = byi[(2 * ti    ) * 8 + qi];
                const uint4 u1 = byi[(2 * ti + 1) * 8 + qi];
                const uint4 v0 = byj[(2 * tj    ) * 8 + qj];
                const uint4 v1 = byj[(2 * tj + 1) * 8 + qj];
                hy00 = acc8(hy00, u0, v0);  hy01 = acc8(hy01, u0, v1);
                hy10 = acc8(hy10, u1, v0);  hy11 = acc8(hy11, u1, v1);
            }
        }

        fx00 += drain(hx00); hx00 = hz;   fx01 += drain(hx01); hx01 = hz;
        fx10 += drain(hx10); hx10 = hz;   fx11 += drain(hx11); hx11 = hz;
        fy00 += drain(hy00); hy00 = hz;   fy01 += drain(hy01); hy01 = hz;
        fy10 += drain(hy10); hy10 = hz;   fy11 += drain(hy11); hy11 = hz;
    }

    float4* gp = g_part + ((size_t)pt * KSPLIT + kc) * (TILE * (TILE / 2));
    gp[(2 * ti    ) * 16 + tj] = make_float4(fx00, fy00, fx01, fy01);
    gp[(2 * ti + 1) * 16 + tj] = make_float4(fx10, fy10, fx11, fy11);

    // ---- per-tile last-block election ----
    __threadfence();
    __syncthreads();
    if (tid == 0) s_ticket = atomicAdd(&g_tilecnt[pt], 1u);
    __syncthreads();
    if (s_ticket != KSPLIT - 1) return;
    if (tid == 0) g_tilecnt[pt] = 0;

    // ---- tile epilogue ----
    const float4* gpt = (const float4*)(g_part + (size_t)pt * KSPLIT * (TILE * (TILE / 2)));
    #pragma unroll
    for (int half = 0; half < 2; half++) {
        const int item = tid + 256 * half;
        const int r  = item >> 4;
        const int cp = item & 15;
        const int ig = bi * TILE + r;
        const int j0 = bj * TILE + 2 * cp;

        const float4* gpr = gpt + r * 16 + cp;
        float4 m = make_float4(0.f, 0.f, 0.f, 0.f);
        #pragma unroll
        for (int kcc = 0; kcc < KSPLIT; kcc++) {
            const float4 v = __ldcg(gpr + (size_t)kcc * (TILE * (TILE / 2)));
            m.x += v.x; m.y += v.y; m.z += v.z; m.w += v.w;
        }
        const float Sxi = g_Sx[ig], Syi = g_Sy[ig];
        const float sx0 = 2.0f * m.x - Sxi - g_Sx[j0];
        const float sy0 = 2.0f * m.y - Syi - g_Sy[j0];
        const float sx1 = 2.0f * m.z - Sxi - g_Sx[j0 + 1];
        const float sy1 = 2.0f * m.w - Syi - g_Sy[j0 + 1];
        const float p0 = sx0 * sy0;
        const float p1 = sx1 * sy1;

        sp[r][2 * cp]     = p0;
        sp[r][2 * cp + 1] = p1;

        float rs = p0 + p1;
        #pragma unroll
        for (int off = 8; off > 0; off >>= 1)
            rs += __shfl_xor_sync(0xffffffffu, rs, off);
        if (cp == 0)
            g_final[ig * NT + bj] = rs;
    }
    __syncthreads();

    if (tid < TILE) {
        float cs = 0.f;
        #pragma unroll
        for (int rr = 0; rr < TILE; rr++) cs += sp[rr][tid];
        g_colpart[pt * TILE + tid] = cs;
    }

    // ---- global last-tile election ----
    __threadfence();
    __syncthreads();
    if (tid == 0) s_ticket = atomicAdd(&g_cnt, 1u);
    __syncthreads();
    if (s_ticket != NPT - 1) return;

    {
        const int i  = tid;
        const int tb = i >> 5;
        const int c  = i & 31;
        float s = 0.f;
        #pragma unroll
        for (int t2 = 0; t2 < NT; t2++)
            if (t2 >= tb) s += __ldcg(&g_final[i * NT + t2]);
        for (int a = 0; a < tb; a++) {
            const int ptc = a * NT - (a * (a - 1)) / 2 + (tb - a);
            s += __ldcg(&g_colpart[ptc * TILE + c]);
        }
        out[i] = -s * (1.0f / ((float)DD * (float)DD));
    }
    __syncthreads();
    if (tid == 0) g_cnt = 0;
}

extern "C" void kernel_launch(void* const* d_in, const int* in_sizes, int n_in,
                              void* d_out, int out_size)
{
    const float* x = (const float*)d_in[0];
    const float* y = (const float*)d_in[1];
    float* out = (float*)d_out;

    conv_kernel<<<2 * BB, 256>>>(x, y);
    pa_kernel<<<NPT * KSPLIT, 256>>>(out);
}